// round 4
// baseline (speedup 1.0000x reference)
#include <cuda_runtime.h>

// Problem constants (fixed by the reference)
constexpr int N  = 100000;
constexpr int E  = 1600000;
constexpr int IN = 32;
constexpr int H  = 64;
constexpr int L  = 16;
constexpr int G  = 64;

constexpr int SCAN_CHUNK = 512;
constexpr int NB_SCAN = (N + SCAN_CHUNK - 1) / SCAN_CHUNK;  // 196

#define CDIV(a, b) (((a) + (b) - 1) / (b))

// ---------------- device scratch (no allocations allowed) ----------------
__device__ float g_buf0[N * H];
__device__ float g_buf1[N * H];
__device__ float g_dinv[N];
__device__ int   g_deg[N];
__device__ int   g_rowptr[N + 1];
__device__ int   g_cursor[N];
__device__ int   g_srcs[E];
__device__ int   g_bsum[256];
__device__ float g_pool[G * H];
__device__ float g_cnt[G];
__device__ float g_z[G * L];

// ---------------- degree histogram ----------------
__global__ void k_hist(const int* __restrict__ dst) {
    int e = blockIdx.x * blockDim.x + threadIdx.x;
    if (e < E) atomicAdd(&g_deg[dst[e]], 1);
}

// ---------------- scan (also computes dinv from deg) ----------------
__global__ void k_scan1() {
    __shared__ int s[SCAN_CHUNK];
    int t = threadIdx.x;
    int i = blockIdx.x * SCAN_CHUNK + t;
    int v = (i < N) ? g_deg[i] : 0;
    if (i < N) g_dinv[i] = rsqrtf((float)v + 1.0f);
    s[t] = v;
    __syncthreads();
#pragma unroll
    for (int off = 1; off < SCAN_CHUNK; off <<= 1) {
        int x = (t >= off) ? s[t - off] : 0;
        __syncthreads();
        s[t] += x;
        __syncthreads();
    }
    if (i < N) g_rowptr[i] = s[t] - v;
    if (t == SCAN_CHUNK - 1) g_bsum[blockIdx.x] = s[t];
}

__global__ void k_scan2() {
    __shared__ int s[256];
    int t = threadIdx.x;
    int v = (t < NB_SCAN) ? g_bsum[t] : 0;
    s[t] = v;
    __syncthreads();
#pragma unroll
    for (int off = 1; off < 256; off <<= 1) {
        int x = (t >= off) ? s[t - off] : 0;
        __syncthreads();
        s[t] += x;
        __syncthreads();
    }
    if (t < NB_SCAN) g_bsum[t] = s[t] - v;
}

__global__ void k_scan3() {
    int i = blockIdx.x * blockDim.x + threadIdx.x;
    if (i < N) {
        int r = g_rowptr[i] + g_bsum[i / SCAN_CHUNK];
        g_rowptr[i] = r;
        g_cursor[i] = r;
    }
    if (i == 0) g_rowptr[N] = E;
}

__global__ void k_fill(const int* __restrict__ src, const int* __restrict__ dst) {
    int e = blockIdx.x * blockDim.x + threadIdx.x;
    if (e >= E) return;
    int pos = atomicAdd(&g_cursor[dst[e]], 1);
    g_srcs[pos] = src[e];
}

// ---------------- prescale: Q0 = x * dinv[row]  (C=32) ----------------
__global__ void k_prescale32(const float* __restrict__ X, float* __restrict__ Y) {
    int idx = blockIdx.x * blockDim.x + threadIdx.x;
    if (idx >= N * 8) return;
    int i = idx >> 3;
    float d = g_dinv[i];
    float4 v = ((const float4*)X)[idx];
    float4 o = {v.x * d, v.y * d, v.z * d, v.w * d};
    ((float4*)Y)[idx] = o;
}

// =====================================================================
// Fused layer kernel: per block of 256 nodes
//   phase 1: A[r] = dinv[r] * (sum_{nbr} X[nbr] + X[r])      (smem)
//   phase 2: acc = A . W  (register-tiled 8x8)
//   epilogue by MODE:
//     0: Y[r] = dinv[r] * relu(acc + bias)       (next layer's Q)
//     1: pool: atomicAdd run-length-reduced relu(acc + bias) into g_pool,
//        counts into g_cnt; no Y write
//     2: Y[r] = acc + bias                        (final output)
// =====================================================================
template <int CIN, int COUT, int MODE>
__global__ void __launch_bounds__(256, 2)
k_fused(const float* __restrict__ X, const float* __restrict__ W,
        const float* __restrict__ bias, float* __restrict__ Y,
        const int* __restrict__ batch) {
    constexpr int ROWS = 256;
    constexpr int APITCH = CIN + 1;     // conflict-free mm-phase reads
    constexpr int QT = CIN / 4;         // threads per node (gather)
    constexpr int NPR = 256 / QT;       // nodes per round
    constexpr int ROUNDS = ROWS / NPR;
    constexpr int CPT = COUT / 8;       // cols per thread (mm)
    extern __shared__ float smem[];
    float* sA = smem;                   // ROWS * APITCH
    float* sW = smem + ROWS * APITCH;   // CIN * COUT

    int t = threadIdx.x;
    int row0 = blockIdx.x * ROWS;

    // load W (float4, coalesced)
    for (int i = t; i < CIN * COUT / 4; i += 256)
        ((float4*)sW)[i] = ((const float4*)W)[i];

    // ---- phase 1: gather into sA
    int q = t % QT, slot = t / QT;
    const float4* Xv = (const float4*)X;
#pragma unroll
    for (int rnd = 0; rnd < ROUNDS; rnd++) {
        int r = rnd * NPR + slot;
        int node = row0 + r;
        float4 acc = make_float4(0.f, 0.f, 0.f, 0.f);
        if (node < N) {
            acc = Xv[(size_t)node * QT + q];
            int beg = g_rowptr[node], end = g_rowptr[node + 1];
#pragma unroll 4
            for (int j = beg; j < end; j++) {
                float4 v = Xv[(size_t)g_srcs[j] * QT + q];
                acc.x += v.x; acc.y += v.y; acc.z += v.z; acc.w += v.w;
            }
            float d = g_dinv[node];
            acc.x *= d; acc.y *= d; acc.z *= d; acc.w *= d;
        }
        float* p = sA + r * APITCH + q * 4;
        p[0] = acc.x; p[1] = acc.y; p[2] = acc.z; p[3] = acc.w;
    }
    __syncthreads();

    // ---- phase 2: register-tiled mm (8 rows x CPT cols per thread)
    int tc = t % 8, tr = t / 8;
    int c0 = tc * CPT, r0 = tr * 8;

    float acc[8][CPT];
#pragma unroll
    for (int i = 0; i < 8; i++)
#pragma unroll
        for (int j = 0; j < CPT; j++) acc[i][j] = 0.0f;

#pragma unroll 8
    for (int k = 0; k < CIN; k++) {
        float a[8];
#pragma unroll
        for (int i = 0; i < 8; i++) a[i] = sA[(r0 + i) * APITCH + k];
        float b[CPT];
#pragma unroll
        for (int v = 0; v < CPT / 4; v++)
            *(float4*)(b + v * 4) = *(const float4*)(sW + k * COUT + c0 + v * 4);
#pragma unroll
        for (int i = 0; i < 8; i++)
#pragma unroll
            for (int j = 0; j < CPT; j++)
                acc[i][j] = fmaf(a[i], b[j], acc[i][j]);
    }

    float bv[CPT];
#pragma unroll
    for (int v = 0; v < CPT / 4; v++)
        *(float4*)(bv + v * 4) = *(const float4*)(bias + c0 + v * 4);

    if (MODE == 1) {
        // pool epilogue: h = relu(acc + b); run-length reduce over the
        // thread's 8 consecutive rows (batch sorted), atomic per run.
        int i0 = 0;
        while (i0 < 8) {
            int row = row0 + r0 + i0;
            if (row >= N) break;
            int g = batch[row];
            float s[CPT];
#pragma unroll
            for (int j = 0; j < CPT; j++)
                s[j] = fmaxf(acc[i0][j] + bv[j], 0.f);
            int i = i0 + 1;
            while (i < 8 && row0 + r0 + i < N && batch[row0 + r0 + i] == g) {
#pragma unroll
                for (int j = 0; j < CPT; j++)
                    s[j] += fmaxf(acc[i][j] + bv[j], 0.f);
                i++;
            }
#pragma unroll
            for (int j = 0; j < CPT; j++)
                atomicAdd(&g_pool[g * H + c0 + j], s[j]);
            if (tc == 0) atomicAdd(&g_cnt[g], (float)(i - i0));
            i0 = i;
        }
    } else {
#pragma unroll
        for (int i = 0; i < 8; i++) {
            int row = row0 + r0 + i;
            if (row >= N) continue;
            float s = (MODE == 0) ? g_dinv[row] : 1.0f;
#pragma unroll
            for (int v = 0; v < CPT / 4; v++) {
                float4 o;
                if (MODE == 0) {
                    o.x = fmaxf(acc[i][v*4+0] + bv[v*4+0], 0.f) * s;
                    o.y = fmaxf(acc[i][v*4+1] + bv[v*4+1], 0.f) * s;
                    o.z = fmaxf(acc[i][v*4+2] + bv[v*4+2], 0.f) * s;
                    o.w = fmaxf(acc[i][v*4+3] + bv[v*4+3], 0.f) * s;
                } else {
                    o.x = acc[i][v*4+0] + bv[v*4+0];
                    o.y = acc[i][v*4+1] + bv[v*4+1];
                    o.z = acc[i][v*4+2] + bv[v*4+2];
                    o.w = acc[i][v*4+3] + bv[v*4+3];
                }
                *(float4*)(Y + (size_t)row * COUT + c0 + v * 4) = o;
            }
        }
    }
}

// ---------------- latent projection: z = mean @ W_proj + b ----------------
__global__ void k_z(const float* __restrict__ Wp, const float* __restrict__ bp,
                    float* __restrict__ out_z) {
    int t = threadIdx.x;  // 1024 = G*L
    int g = t / L, l = t % L;
    float inv = 1.0f / fmaxf(g_cnt[g], 1.0f);
    float acc = bp[l];
#pragma unroll
    for (int c = 0; c < H; c++) acc = fmaf(g_pool[g * H + c] * inv, Wp[c * L + l], acc);
    g_z[t] = acc;
    out_z[t] = acc;
}

// ------- decoder broadcast: Qd = dinv * relu(z[batch] @ W_dec_proj + b) -------
__global__ void k_dec_bcast(const int* __restrict__ batch, const float* __restrict__ W,
                            const float* __restrict__ b, float* __restrict__ Y) {
    int idx = blockIdx.x * blockDim.x + threadIdx.x;  // N * 16
    if (idx >= N * 16) return;
    int i = idx >> 4, v = idx & 15;
    int gid = batch[i];
    float4 acc = ((const float4*)b)[v];
#pragma unroll
    for (int l = 0; l < L; l++) {
        float zl = g_z[gid * L + l];
        float4 w = ((const float4*)W)[l * 16 + v];
        acc.x = fmaf(zl, w.x, acc.x); acc.y = fmaf(zl, w.y, acc.y);
        acc.z = fmaf(zl, w.z, acc.z); acc.w = fmaf(zl, w.w, acc.w);
    }
    float d = g_dinv[i];
    acc.x = fmaxf(acc.x, 0.f) * d; acc.y = fmaxf(acc.y, 0.f) * d;
    acc.z = fmaxf(acc.z, 0.f) * d; acc.w = fmaxf(acc.w, 0.f) * d;
    ((float4*)Y)[idx] = acc;
}

// ---------------- launcher ----------------
extern "C" void kernel_launch(void* const* d_in, const int* in_sizes, int n_in,
                              void* d_out, int out_size) {
    const float* x       = (const float*)d_in[0];
    const int*   ei      = (const int*)d_in[1];
    const int*   src     = ei;
    const int*   dst     = ei + E;
    const int*   batch   = (const int*)d_in[2];
    const float* W_enc0  = (const float*)d_in[3];
    const float* b_enc0  = (const float*)d_in[4];
    const float* W_enc1  = (const float*)d_in[5];
    const float* b_enc1  = (const float*)d_in[6];
    const float* W_enc2  = (const float*)d_in[7];
    const float* b_enc2  = (const float*)d_in[8];
    const float* W_proj  = (const float*)d_in[9];
    const float* b_proj  = (const float*)d_in[10];
    const float* W_dproj = (const float*)d_in[11];
    const float* b_dproj = (const float*)d_in[12];
    const float* W_dec0  = (const float*)d_in[13];
    const float* b_dec0  = (const float*)d_in[14];
    const float* W_dec1  = (const float*)d_in[15];
    const float* b_dec1  = (const float*)d_in[16];

    float* out_recon = (float*)d_out;           // [N, IN]
    float* out_z     = (float*)d_out + N * IN;  // [G, L]

    float* buf0;  cudaGetSymbolAddress((void**)&buf0, g_buf0);
    float* buf1;  cudaGetSymbolAddress((void**)&buf1, g_buf1);
    int*   degp;  cudaGetSymbolAddress((void**)&degp, g_deg);
    float* poolp; cudaGetSymbolAddress((void**)&poolp, g_pool);
    float* cntp;  cudaGetSymbolAddress((void**)&cntp, g_cnt);

    const int T = 256;

    constexpr int SM_32_64 = (256 * 33 + 32 * 64) * 4;   // 41.0 KB
    constexpr int SM_64_64 = (256 * 65 + 64 * 64) * 4;   // 81.0 KB
    constexpr int SM_64_32 = (256 * 65 + 64 * 32) * 4;   // 73.0 KB
    static bool attr_done = false;
    if (!attr_done) {
        cudaFuncSetAttribute((const void*)k_fused<IN, H, 0>,
                             cudaFuncAttributeMaxDynamicSharedMemorySize, SM_32_64);
        cudaFuncSetAttribute((const void*)k_fused<H, H, 0>,
                             cudaFuncAttributeMaxDynamicSharedMemorySize, SM_64_64);
        cudaFuncSetAttribute((const void*)k_fused<H, H, 1>,
                             cudaFuncAttributeMaxDynamicSharedMemorySize, SM_64_64);
        cudaFuncSetAttribute((const void*)k_fused<H, IN, 2>,
                             cudaFuncAttributeMaxDynamicSharedMemorySize, SM_64_32);
        attr_done = true;
    }

    // ---- CSR build + dinv
    cudaMemsetAsync(degp, 0, N * sizeof(int));
    k_hist<<<CDIV(E, T), T>>>(dst);
    k_scan1<<<NB_SCAN, SCAN_CHUNK>>>();
    k_scan2<<<1, 256>>>();
    k_scan3<<<CDIV(N, T), T>>>();
    k_fill<<<CDIV(E, T), T>>>(src, dst);

    // zero pool accumulators (used later; issue early, off critical path)
    cudaMemsetAsync(poolp, 0, G * H * sizeof(float));
    cudaMemsetAsync(cntp, 0, G * sizeof(float));

    const int FB = CDIV(N, 256);

    // ---- enc0: Q0 = dinv*x, fused gather+mm -> Q1
    k_prescale32<<<CDIV(N * 8, T), T>>>(x, buf0);
    k_fused<IN, H, 0><<<FB, 256, SM_32_64>>>(buf0, W_enc0, b_enc0, buf1, nullptr);

    // ---- enc1: fused -> Q2
    k_fused<H, H, 0><<<FB, 256, SM_64_64>>>(buf1, W_enc1, b_enc1, buf0, nullptr);

    // ---- enc2: fused, pool epilogue (no gmem activation write)
    k_fused<H, H, 1><<<FB, 256, SM_64_64>>>(buf0, W_enc2, b_enc2, nullptr, batch);

    // ---- latent projection
    k_z<<<1, G * L>>>(W_proj, b_proj, out_z);

    // ---- decoder broadcast (pre-scaled by dinv)
    k_dec_bcast<<<CDIV(N * 16, T), T>>>(batch, W_dproj, b_dproj, buf0);

    // ---- dec0: fused -> Qe
    k_fused<H, H, 0><<<FB, 256, SM_64_64>>>(buf0, W_dec0, b_dec0, buf1, nullptr);

    // ---- dec1: fused, final output (bias, no relu, no scale)
    k_fused<H, IN, 2><<<FB, 256, SM_64_32>>>(buf1, W_dec1, b_dec1, out_recon, nullptr);
}

// round 5
// speedup vs baseline: 1.3476x; 1.3476x over previous
#include <cuda_runtime.h>
#include <cuda_fp16.h>

// Problem constants (fixed by the reference)
constexpr int N  = 100000;
constexpr int E  = 1600000;
constexpr int IN = 32;
constexpr int H  = 64;
constexpr int L  = 16;
constexpr int G  = 64;

constexpr int SCAN_CHUNK = 512;
constexpr int NB_SCAN = (N + SCAN_CHUNK - 1) / SCAN_CHUNK;  // 196

#define CDIV(a, b) (((a) + (b) - 1) / (b))

// ---------------- device scratch (no allocations allowed) ----------------
__device__ float  g_buf0[N * H];
__device__ float  g_buf1[N * H];
__device__ __half g_half[N * H];   // fp16 gather inputs (X' tensors)
__device__ float  g_dinv[N];
__device__ int    g_deg[N];
__device__ int    g_rowptr[N + 1];
__device__ int    g_cursor[N];
__device__ int    g_srcs[E];
__device__ int    g_bsum[256];
__device__ float  g_pool[G * H];
__device__ float  g_cnt[G];
__device__ float  g_z[G * L];

struct alignas(16) H8 { __half2 h[4]; };   // 8 halves = 16 bytes

// ---------------- degree histogram ----------------
__global__ void k_hist(const int* __restrict__ dst) {
    int e = blockIdx.x * blockDim.x + threadIdx.x;
    if (e < E) atomicAdd(&g_deg[dst[e]], 1);
}

// ---------------- scan pass 1 (also computes dinv) ----------------
__global__ void k_scan1() {
    __shared__ int s[SCAN_CHUNK];
    int t = threadIdx.x;
    int i = blockIdx.x * SCAN_CHUNK + t;
    int v = (i < N) ? g_deg[i] : 0;
    if (i < N) g_dinv[i] = rsqrtf((float)v + 1.0f);
    s[t] = v;
    __syncthreads();
#pragma unroll
    for (int off = 1; off < SCAN_CHUNK; off <<= 1) {
        int x = (t >= off) ? s[t - off] : 0;
        __syncthreads();
        s[t] += x;
        __syncthreads();
    }
    if (i < N) g_rowptr[i] = s[t] - v;
    if (t == SCAN_CHUNK - 1) g_bsum[blockIdx.x] = s[t];
}

// ---------------- fused scan2+scan3: every block scans bsum in smem ----------------
__global__ void k_scan23() {
    __shared__ int s[256];
    __shared__ int excl[256];
    int t = threadIdx.x;
    int v = (t < NB_SCAN) ? g_bsum[t] : 0;
    s[t] = v;
    __syncthreads();
#pragma unroll
    for (int off = 1; off < 256; off <<= 1) {
        int x = (t >= off) ? s[t - off] : 0;
        __syncthreads();
        s[t] += x;
        __syncthreads();
    }
    excl[t] = s[t] - v;
    __syncthreads();
    int i = blockIdx.x * blockDim.x + t;
    if (i < N) {
        int r = g_rowptr[i] + excl[i / SCAN_CHUNK];
        g_rowptr[i] = r;
        g_cursor[i] = r;
    }
    if (i == 0) g_rowptr[N] = E;
}

__global__ void k_fill(const int* __restrict__ src, const int* __restrict__ dst) {
    int e = blockIdx.x * blockDim.x + threadIdx.x;
    if (e >= E) return;
    int pos = atomicAdd(&g_cursor[dst[e]], 1);
    g_srcs[pos] = src[e];
}

// ---------------- prescale -> fp16: Q0 = half(x * dinv[row])  (C=32) ----------------
__global__ void k_prescale16(const float* __restrict__ X, __half* __restrict__ Y) {
    int idx = blockIdx.x * blockDim.x + threadIdx.x;   // N*4, each does 8 floats
    if (idx >= N * 4) return;
    int i = idx >> 2;
    float d = g_dinv[i];
    float4 a = ((const float4*)X)[idx * 2 + 0];
    float4 b = ((const float4*)X)[idx * 2 + 1];
    H8 o;
    o.h[0] = __floats2half2_rn(a.x * d, a.y * d);
    o.h[1] = __floats2half2_rn(a.z * d, a.w * d);
    o.h[2] = __floats2half2_rn(b.x * d, b.y * d);
    o.h[3] = __floats2half2_rn(b.z * d, b.w * d);
    ((H8*)Y)[idx] = o;
}

// ------- CSR gather (fp16 in, fp32 out):  Y[i] = dinv[i]*(sum X[s] + X[i]) (+bias,relu) -------
template <int C, bool BIAS, bool RELU>
__global__ void k_gather16(const __half* __restrict__ X, const float* __restrict__ bias,
                           float* __restrict__ Y) {
    constexpr int Q = C / 8;                 // threads per node (8 halves each)
    constexpr int NPB = 256 / Q;
    int t = threadIdx.x;
    int node = blockIdx.x * NPB + t / Q;
    int q = t % Q;
    if (node >= N) return;
    int beg = g_rowptr[node];
    int end = g_rowptr[node + 1];
    const H8* Xv = (const H8*)X;
    float2 acc[4];
    {
        H8 v = Xv[(size_t)node * Q + q];     // self term (already dinv-scaled)
#pragma unroll
        for (int k = 0; k < 4; k++) acc[k] = __half22float2(v.h[k]);
    }
#pragma unroll 4
    for (int j = beg; j < end; j++) {
        int s = g_srcs[j];
        H8 v = Xv[(size_t)s * Q + q];
#pragma unroll
        for (int k = 0; k < 4; k++) {
            float2 f = __half22float2(v.h[k]);
            acc[k].x += f.x; acc[k].y += f.y;
        }
    }
    float d = g_dinv[node];
    float o[8];
#pragma unroll
    for (int k = 0; k < 4; k++) { o[2*k] = acc[k].x * d; o[2*k+1] = acc[k].y * d; }
    if (BIAS) {
        const float* bp = bias + q * 8;
#pragma unroll
        for (int k = 0; k < 8; k++) o[k] += bp[k];
    }
    if (RELU) {
#pragma unroll
        for (int k = 0; k < 8; k++) o[k] = fmaxf(o[k], 0.f);
    }
    float4* out = (float4*)(Y + (size_t)node * C + q * 8);
    out[0] = make_float4(o[0], o[1], o[2], o[3]);
    out[1] = make_float4(o[4], o[5], o[6], o[7]);
}

// ---------------- register-tiled per-node matmul (fp32 in) ----------------
// HALFOUT: write fp16 (X' for the next gather). SCALE: multiply by dinv[row].
template <int CIN, int COUT, bool SCALE, bool BIAS, bool RELU, bool HALFOUT>
__global__ void __launch_bounds__(256, 2)
k_mm(const float* __restrict__ X, const float* __restrict__ W,
     const float* __restrict__ bias, void* __restrict__ Yv) {
    constexpr int ROWS = 256;
    constexpr int CPT = COUT / 8;
    constexpr int XPITCH = CIN + 1;
    extern __shared__ float smem[];
    float* sX = smem;
    float* sW = smem + ROWS * XPITCH;

    int t = threadIdx.x;
    int row0 = blockIdx.x * ROWS;

    for (int i = t; i < CIN * COUT / 4; i += 256)
        ((float4*)sW)[i] = ((const float4*)W)[i];
    for (int i = t; i < ROWS * CIN; i += 256) {
        int r = i / CIN, k = i % CIN;
        int row = row0 + r;
        sX[r * XPITCH + k] = (row < N) ? X[(size_t)row * CIN + k] : 0.0f;
    }
    __syncthreads();

    int tc = t % 8, tr = t / 8;
    int c0 = tc * CPT, r0 = tr * 8;

    float acc[8][CPT];
#pragma unroll
    for (int i = 0; i < 8; i++)
#pragma unroll
        for (int j = 0; j < CPT; j++) acc[i][j] = 0.0f;

#pragma unroll 8
    for (int k = 0; k < CIN; k++) {
        float a[8];
#pragma unroll
        for (int i = 0; i < 8; i++) a[i] = sX[(r0 + i) * XPITCH + k];
        float b[CPT];
#pragma unroll
        for (int v = 0; v < CPT / 4; v++)
            *(float4*)(b + v * 4) = *(const float4*)(sW + k * COUT + c0 + v * 4);
#pragma unroll
        for (int i = 0; i < 8; i++)
#pragma unroll
            for (int j = 0; j < CPT; j++)
                acc[i][j] = fmaf(a[i], b[j], acc[i][j]);
    }

    float bv[CPT];
    if (BIAS) {
#pragma unroll
        for (int v = 0; v < CPT / 4; v++)
            *(float4*)(bv + v * 4) = *(const float4*)(bias + c0 + v * 4);
    }
#pragma unroll
    for (int i = 0; i < 8; i++) {
        int row = row0 + r0 + i;
        if (row >= N) continue;
        float s = SCALE ? g_dinv[row] : 1.0f;
        float o[CPT];
#pragma unroll
        for (int j = 0; j < CPT; j++) {
            float v = acc[i][j] * s;
            if (BIAS) v += bv[j];
            if (RELU) v = fmaxf(v, 0.f);
            o[j] = v;
        }
        if (HALFOUT) {
            __half* Y = (__half*)Yv;
            if (CPT == 8) {
                H8 h;
#pragma unroll
                for (int k = 0; k < 4; k++) h.h[k] = __floats2half2_rn(o[2*k], o[2*k+1]);
                *(H8*)(Y + (size_t)row * COUT + c0) = h;
            } else {
                __half2 h0 = __floats2half2_rn(o[0], o[1]);
                __half2 h1 = __floats2half2_rn(o[2], o[3]);
                *(__half2*)(Y + (size_t)row * COUT + c0) = h0;
                *(__half2*)(Y + (size_t)row * COUT + c0 + 2) = h1;
            }
        } else {
            float* Y = (float*)Yv;
#pragma unroll
            for (int v = 0; v < CPT / 4; v++)
                *(float4*)(Y + (size_t)row * COUT + c0 + v * 4) =
                    make_float4(o[v*4+0], o[v*4+1], o[v*4+2], o[v*4+3]);
        }
    }
}

// ---------------- global mean pool (sorted batch, run-length) + counts ----------------
__global__ void k_pool_acc(const int* __restrict__ batch, const float* __restrict__ Hf) {
    int t = threadIdx.x;
    int c = t % 64;
    int base = blockIdx.x * 128;
    float acc = 0.f;
    float cntacc = 0.f;
    int cur = -1;
    for (int j = t / 64; j < 128; j += 4) {
        int i = base + j;
        if (i >= N) break;
        int g = batch[i];
        if (g != cur) {
            if (cur >= 0) {
                atomicAdd(&g_pool[cur * 64 + c], acc);
                if (c == 0) atomicAdd(&g_cnt[cur], cntacc);
            }
            cur = g; acc = 0.f; cntacc = 0.f;
        }
        acc += Hf[(size_t)i * 64 + c];
        cntacc += 1.f;
    }
    if (cur >= 0) {
        atomicAdd(&g_pool[cur * 64 + c], acc);
        if (c == 0) atomicAdd(&g_cnt[cur], cntacc);
    }
}

// ---------------- latent projection: z = mean @ W_proj + b ----------------
__global__ void k_z(const float* __restrict__ Wp, const float* __restrict__ bp,
                    float* __restrict__ out_z) {
    int t = threadIdx.x;  // 1024 = G*L
    int g = t / L, l = t % L;
    float inv = 1.0f / fmaxf(g_cnt[g], 1.0f);
    float acc = bp[l];
#pragma unroll
    for (int c = 0; c < H; c++) acc = fmaf(g_pool[g * H + c] * inv, Wp[c * L + l], acc);
    g_z[t] = acc;
    out_z[t] = acc;
}

// ------- decoder broadcast: h_d = relu(z[batch] @ W_dec_proj + b)  (fp32) -------
__global__ void k_dec_bcast(const int* __restrict__ batch, const float* __restrict__ W,
                            const float* __restrict__ b, float* __restrict__ Y) {
    int idx = blockIdx.x * blockDim.x + threadIdx.x;  // N * 16
    if (idx >= N * 16) return;
    int i = idx >> 4, v = idx & 15;
    int gid = batch[i];
    float4 acc = ((const float4*)b)[v];
#pragma unroll
    for (int l = 0; l < L; l++) {
        float zl = g_z[gid * L + l];
        float4 w = ((const float4*)W)[l * 16 + v];
        acc.x = fmaf(zl, w.x, acc.x); acc.y = fmaf(zl, w.y, acc.y);
        acc.z = fmaf(zl, w.z, acc.z); acc.w = fmaf(zl, w.w, acc.w);
    }
    acc.x = fmaxf(acc.x, 0.f); acc.y = fmaxf(acc.y, 0.f);
    acc.z = fmaxf(acc.z, 0.f); acc.w = fmaxf(acc.w, 0.f);
    ((float4*)Y)[idx] = acc;
}

// ---------------- launcher ----------------
extern "C" void kernel_launch(void* const* d_in, const int* in_sizes, int n_in,
                              void* d_out, int out_size) {
    const float* x       = (const float*)d_in[0];
    const int*   ei      = (const int*)d_in[1];
    const int*   src     = ei;
    const int*   dst     = ei + E;
    const int*   batch   = (const int*)d_in[2];
    const float* W_enc0  = (const float*)d_in[3];
    const float* b_enc0  = (const float*)d_in[4];
    const float* W_enc1  = (const float*)d_in[5];
    const float* b_enc1  = (const float*)d_in[6];
    const float* W_enc2  = (const float*)d_in[7];
    const float* b_enc2  = (const float*)d_in[8];
    const float* W_proj  = (const float*)d_in[9];
    const float* b_proj  = (const float*)d_in[10];
    const float* W_dproj = (const float*)d_in[11];
    const float* b_dproj = (const float*)d_in[12];
    const float* W_dec0  = (const float*)d_in[13];
    const float* b_dec0  = (const float*)d_in[14];
    const float* W_dec1  = (const float*)d_in[15];
    const float* b_dec1  = (const float*)d_in[16];

    float* out_recon = (float*)d_out;           // [N, IN]
    float* out_z     = (float*)d_out + N * IN;  // [G, L]

    float*  buf0;  cudaGetSymbolAddress((void**)&buf0, g_buf0);
    float*  buf1;  cudaGetSymbolAddress((void**)&buf1, g_buf1);
    __half* hbuf;  cudaGetSymbolAddress((void**)&hbuf, g_half);
    int*    degp;  cudaGetSymbolAddress((void**)&degp, g_deg);
    float*  poolp; cudaGetSymbolAddress((void**)&poolp, g_pool);
    float*  cntp;  cudaGetSymbolAddress((void**)&cntp, g_cnt);

    const int T = 256;

    constexpr int SM_32_64 = (256 * 33 + 32 * 64) * 4;   // 41.0 KB
    constexpr int SM_64_64 = (256 * 65 + 64 * 64) * 4;   // 81.0 KB
    constexpr int SM_64_32 = (256 * 65 + 64 * 32) * 4;   // 73.0 KB
    static bool attr_done = false;
    if (!attr_done) {
        cudaFuncSetAttribute((const void*)k_mm<IN, H, false, true, true, false>,
                             cudaFuncAttributeMaxDynamicSharedMemorySize, SM_32_64);
        cudaFuncSetAttribute((const void*)k_mm<H, H, true, false, false, true>,
                             cudaFuncAttributeMaxDynamicSharedMemorySize, SM_64_64);
        cudaFuncSetAttribute((const void*)k_mm<H, IN, true, false, false, true>,
                             cudaFuncAttributeMaxDynamicSharedMemorySize, SM_64_32);
        attr_done = true;
    }

    // ---- CSR build + dinv
    cudaMemsetAsync(degp, 0, N * sizeof(int));
    cudaMemsetAsync(poolp, 0, G * H * sizeof(float));
    cudaMemsetAsync(cntp, 0, G * sizeof(float));
    k_hist<<<CDIV(E, T), T>>>(dst);
    k_scan1<<<NB_SCAN, SCAN_CHUNK>>>();
    k_scan23<<<CDIV(N, T), T>>>();
    k_fill<<<CDIV(E, T), T>>>(src, dst);

    const int MMB = CDIV(N, 256);

    // ---- enc0: Q0 = half(dinv*x); gather C=32; mm 32->64 (+bias+relu) -> h1
    k_prescale16<<<CDIV(N * 4, T), T>>>(x, hbuf);
    k_gather16<IN, false, false><<<CDIV(N, 64), 256>>>(hbuf, nullptr, buf0);
    k_mm<IN, H, false, true, true, false><<<MMB, 256, SM_32_64>>>(buf0, W_enc0, b_enc0, buf1);

    // ---- enc1: mm (dinv-scaled, fp16 out); gather (+bias+relu) -> h2
    k_mm<H, H, true, false, false, true><<<MMB, 256, SM_64_64>>>(buf1, W_enc1, nullptr, hbuf);
    k_gather16<H, true, true><<<CDIV(N, 32), 256>>>(hbuf, b_enc1, buf0);

    // ---- enc2
    k_mm<H, H, true, false, false, true><<<MMB, 256, SM_64_64>>>(buf0, W_enc2, nullptr, hbuf);
    k_gather16<H, true, true><<<CDIV(N, 32), 256>>>(hbuf, b_enc2, buf1);

    // ---- global mean pool + latent projection
    k_pool_acc<<<CDIV(N, 128), 256>>>(batch, buf1);
    k_z<<<1, G * L>>>(W_proj, b_proj, out_z);

    // ---- decoder broadcast -> h_d
    k_dec_bcast<<<CDIV(N * 16, T), T>>>(batch, W_dproj, b_dproj, buf0);

    // ---- dec0
    k_mm<H, H, true, false, false, true><<<MMB, 256, SM_64_64>>>(buf0, W_dec0, nullptr, hbuf);
    k_gather16<H, true, true><<<CDIV(N, 32), 256>>>(hbuf, b_dec0, buf1);

    // ---- dec1: mm 64->32 (dinv-scaled, fp16 out); gather C=32 (+bias) -> out
    k_mm<H, IN, true, false, false, true><<<MMB, 256, SM_64_32>>>(buf1, W_dec1, nullptr, hbuf);
    k_gather16<IN, true, false><<<CDIV(N, 64), 256>>>(hbuf, b_dec1, out_recon);
}

// round 6
// speedup vs baseline: 1.5616x; 1.1588x over previous
#include <cuda_runtime.h>

// Problem constants (fixed by the reference)
constexpr int N  = 100000;
constexpr int E  = 1600000;
constexpr int IN = 32;
constexpr int H  = 64;
constexpr int L  = 16;
constexpr int G  = 64;

constexpr int SCAN_CHUNK = 512;
constexpr int NB_SCAN = (N + SCAN_CHUNK - 1) / SCAN_CHUNK;  // 196

#define CDIV(a, b) (((a) + (b) - 1) / (b))

typedef unsigned long long ull;

// ---------------- packed f32x2 helpers (FFMA2 — ptxas never emits this) ----------------
__device__ __forceinline__ ull pack2(float x, float y) {
    ull r;
    asm("mov.b64 %0, {%1, %2};" : "=l"(r) : "f"(x), "f"(y));
    return r;
}
__device__ __forceinline__ void unpack2(float& x, float& y, ull v) {
    asm("mov.b64 {%0, %1}, %2;" : "=f"(x), "=f"(y) : "l"(v));
}
__device__ __forceinline__ void fma2(ull& d, ull a, ull b) {
    asm("fma.rn.f32x2 %0, %1, %2, %0;" : "+l"(d) : "l"(a), "l"(b));
}

// ---------------- device scratch (no allocations allowed) ----------------
__device__ float g_buf0[N * H];
__device__ float g_buf1[N * H];
__device__ float g_dinv[N];
__device__ int   g_deg[N];
__device__ int   g_rowptr[N + 1];
__device__ int   g_cursor[N];
__device__ int   g_srcs[E];
__device__ int   g_bsum[256];
__device__ float g_pool[G * H];
__device__ float g_cnt[G];
__device__ float g_z[G * L];

// ---------------- degree histogram ----------------
__global__ void k_hist(const int* __restrict__ dst) {
    int e = blockIdx.x * blockDim.x + threadIdx.x;
    if (e < E) atomicAdd(&g_deg[dst[e]], 1);
}

// ---------------- scan pass 1 (also computes dinv) ----------------
__global__ void k_scan1() {
    __shared__ int s[SCAN_CHUNK];
    int t = threadIdx.x;
    int i = blockIdx.x * SCAN_CHUNK + t;
    int v = (i < N) ? g_deg[i] : 0;
    if (i < N) g_dinv[i] = rsqrtf((float)v + 1.0f);
    s[t] = v;
    __syncthreads();
#pragma unroll
    for (int off = 1; off < SCAN_CHUNK; off <<= 1) {
        int x = (t >= off) ? s[t - off] : 0;
        __syncthreads();
        s[t] += x;
        __syncthreads();
    }
    if (i < N) g_rowptr[i] = s[t] - v;
    if (t == SCAN_CHUNK - 1) g_bsum[blockIdx.x] = s[t];
}

// ---------------- fused scan2+scan3 ----------------
__global__ void k_scan23() {
    __shared__ int s[256];
    __shared__ int excl[256];
    int t = threadIdx.x;
    int v = (t < NB_SCAN) ? g_bsum[t] : 0;
    s[t] = v;
    __syncthreads();
#pragma unroll
    for (int off = 1; off < 256; off <<= 1) {
        int x = (t >= off) ? s[t - off] : 0;
        __syncthreads();
        s[t] += x;
        __syncthreads();
    }
    excl[t] = s[t] - v;
    __syncthreads();
    int i = blockIdx.x * blockDim.x + t;
    if (i < N) {
        int r = g_rowptr[i] + excl[i / SCAN_CHUNK];
        g_rowptr[i] = r;
        g_cursor[i] = r;
    }
    if (i == 0) g_rowptr[N] = E;
}

__global__ void k_fill(const int* __restrict__ src, const int* __restrict__ dst) {
    int e = blockIdx.x * blockDim.x + threadIdx.x;
    if (e >= E) return;
    int pos = atomicAdd(&g_cursor[dst[e]], 1);
    g_srcs[pos] = src[e];
}

// ---------------- prescale: Q0 = x * dinv[row]  (C=32) ----------------
__global__ void k_prescale32(const float* __restrict__ X, float* __restrict__ Y) {
    int idx = blockIdx.x * blockDim.x + threadIdx.x;
    if (idx >= N * 8) return;
    int i = idx >> 3;
    float d = g_dinv[i];
    float4 v = ((const float4*)X)[idx];
    float4 o = {v.x * d, v.y * d, v.z * d, v.w * d};
    ((float4*)Y)[idx] = o;
}

// ---------------- CSR gather:  Y[i] = dinv[i]*(sum_src X[src] + X[i]) ----------------
template <int C, bool BIAS, bool RELU>
__global__ void k_gather(const float* __restrict__ X, const float* __restrict__ bias,
                         float* __restrict__ Y) {
    constexpr int Q = C / 4;
    constexpr int NPB = 256 / Q;
    int t = threadIdx.x;
    int node = blockIdx.x * NPB + t / Q;
    int q = t % Q;
    if (node >= N) return;
    int beg = g_rowptr[node];
    int end = g_rowptr[node + 1];
    const float4* Xv = (const float4*)X;
    float4 acc = Xv[(size_t)node * Q + q];
#pragma unroll 4
    for (int j = beg; j < end; j++) {
        int s = g_srcs[j];
        float4 v = Xv[(size_t)s * Q + q];
        acc.x += v.x; acc.y += v.y; acc.z += v.z; acc.w += v.w;
    }
    float d = g_dinv[node];
    acc.x *= d; acc.y *= d; acc.z *= d; acc.w *= d;
    if (BIAS) {
        float4 bv = ((const float4*)bias)[q];
        acc.x += bv.x; acc.y += bv.y; acc.z += bv.z; acc.w += bv.w;
    }
    if (RELU) {
        acc.x = fmaxf(acc.x, 0.f); acc.y = fmaxf(acc.y, 0.f);
        acc.z = fmaxf(acc.z, 0.f); acc.w = fmaxf(acc.w, 0.f);
    }
    ((float4*)Y)[(size_t)node * Q + q] = acc;
}

// ---------------- register-tiled per-node matmul with packed f32x2 FMA ----------------
template <int CIN, int COUT, bool SCALE, bool BIAS, bool RELU>
__global__ void __launch_bounds__(256, 2)
k_mm(const float* __restrict__ X, const float* __restrict__ W,
     const float* __restrict__ bias, float* __restrict__ Y) {
    constexpr int ROWS = 256;
    constexpr int CPT = COUT / 8;       // 8 for COUT=64, 4 for COUT=32
    constexpr int CP2 = CPT / 2;        // packed pairs per thread
    constexpr int XPITCH = CIN + 1;
    extern __shared__ float smem[];
    float* sX = smem;
    float* sW = smem + ROWS * XPITCH;

    int t = threadIdx.x;
    int row0 = blockIdx.x * ROWS;

    for (int i = t; i < CIN * COUT / 4; i += 256)
        ((float4*)sW)[i] = ((const float4*)W)[i];
    for (int i = t; i < ROWS * CIN; i += 256) {
        int r = i / CIN, k = i % CIN;
        int row = row0 + r;
        sX[r * XPITCH + k] = (row < N) ? X[(size_t)row * CIN + k] : 0.0f;
    }
    __syncthreads();

    int tc = t % 8, tr = t / 8;
    int c0 = tc * CPT, r0 = tr * 8;

    ull acc2[8][CP2];
    const ull zz = pack2(0.f, 0.f);
#pragma unroll
    for (int i = 0; i < 8; i++)
#pragma unroll
        for (int j = 0; j < CP2; j++) acc2[i][j] = zz;

#pragma unroll 8
    for (int k = 0; k < CIN; k++) {
        ull a2[8];
#pragma unroll
        for (int i = 0; i < 8; i++) {
            float av = sX[(r0 + i) * XPITCH + k];
            a2[i] = pack2(av, av);
        }
        ull b2[CP2];
#pragma unroll
        for (int v = 0; v < CPT / 4; v++) {
            ulonglong2 bb = *(const ulonglong2*)(sW + k * COUT + c0 + v * 4);
            b2[v * 2 + 0] = bb.x;
            b2[v * 2 + 1] = bb.y;
        }
#pragma unroll
        for (int i = 0; i < 8; i++)
#pragma unroll
            for (int j = 0; j < CP2; j++)
                fma2(acc2[i][j], a2[i], b2[j]);
    }

    float bv[CPT];
    if (BIAS) {
#pragma unroll
        for (int v = 0; v < CPT / 4; v++)
            *(float4*)(bv + v * 4) = *(const float4*)(bias + c0 + v * 4);
    }
#pragma unroll
    for (int i = 0; i < 8; i++) {
        int row = row0 + r0 + i;
        if (row >= N) continue;
        float s = SCALE ? g_dinv[row] : 1.0f;
        float o[CPT];
#pragma unroll
        for (int j = 0; j < CP2; j++) unpack2(o[2 * j], o[2 * j + 1], acc2[i][j]);
#pragma unroll
        for (int j = 0; j < CPT; j++) {
            float v = o[j] * s;
            if (BIAS) v += bv[j];
            if (RELU) v = fmaxf(v, 0.f);
            o[j] = v;
        }
#pragma unroll
        for (int v = 0; v < CPT / 4; v++)
            *(float4*)(Y + (size_t)row * COUT + c0 + v * 4) =
                make_float4(o[v*4+0], o[v*4+1], o[v*4+2], o[v*4+3]);
    }
}

// ---------------- global mean pool (sorted batch, run-length) + counts ----------------
__global__ void k_pool_acc(const int* __restrict__ batch, const float* __restrict__ Hf) {
    int t = threadIdx.x;
    int c = t % 64;
    int base = blockIdx.x * 128;
    float acc = 0.f;
    float cntacc = 0.f;
    int cur = -1;
    for (int j = t / 64; j < 128; j += 4) {
        int i = base + j;
        if (i >= N) break;
        int g = batch[i];
        if (g != cur) {
            if (cur >= 0) {
                atomicAdd(&g_pool[cur * 64 + c], acc);
                if (c == 0) atomicAdd(&g_cnt[cur], cntacc);
            }
            cur = g; acc = 0.f; cntacc = 0.f;
        }
        acc += Hf[(size_t)i * 64 + c];
        cntacc += 1.f;
    }
    if (cur >= 0) {
        atomicAdd(&g_pool[cur * 64 + c], acc);
        if (c == 0) atomicAdd(&g_cnt[cur], cntacc);
    }
}

// ---------------- latent projection: z = mean @ W_proj + b ----------------
__global__ void k_z(const float* __restrict__ Wp, const float* __restrict__ bp,
                    float* __restrict__ out_z) {
    int t = threadIdx.x;  // 1024 = G*L
    int g = t / L, l = t % L;
    float inv = 1.0f / fmaxf(g_cnt[g], 1.0f);
    float acc = bp[l];
#pragma unroll
    for (int c = 0; c < H; c++) acc = fmaf(g_pool[g * H + c] * inv, Wp[c * L + l], acc);
    g_z[t] = acc;
    out_z[t] = acc;
}

// ------- decoder broadcast: h_d = relu(z[batch] @ W_dec_proj + b) -------
__global__ void k_dec_bcast(const int* __restrict__ batch, const float* __restrict__ W,
                            const float* __restrict__ b, float* __restrict__ Y) {
    int idx = blockIdx.x * blockDim.x + threadIdx.x;  // N * 16
    if (idx >= N * 16) return;
    int i = idx >> 4, v = idx & 15;
    int gid = batch[i];
    float4 acc = ((const float4*)b)[v];
#pragma unroll
    for (int l = 0; l < L; l++) {
        float zl = g_z[gid * L + l];
        float4 w = ((const float4*)W)[l * 16 + v];
        acc.x = fmaf(zl, w.x, acc.x); acc.y = fmaf(zl, w.y, acc.y);
        acc.z = fmaf(zl, w.z, acc.z); acc.w = fmaf(zl, w.w, acc.w);
    }
    acc.x = fmaxf(acc.x, 0.f); acc.y = fmaxf(acc.y, 0.f);
    acc.z = fmaxf(acc.z, 0.f); acc.w = fmaxf(acc.w, 0.f);
    ((float4*)Y)[idx] = acc;
}

// ---------------- launcher ----------------
extern "C" void kernel_launch(void* const* d_in, const int* in_sizes, int n_in,
                              void* d_out, int out_size) {
    const float* x       = (const float*)d_in[0];
    const int*   ei      = (const int*)d_in[1];
    const int*   src     = ei;
    const int*   dst     = ei + E;
    const int*   batch   = (const int*)d_in[2];
    const float* W_enc0  = (const float*)d_in[3];
    const float* b_enc0  = (const float*)d_in[4];
    const float* W_enc1  = (const float*)d_in[5];
    const float* b_enc1  = (const float*)d_in[6];
    const float* W_enc2  = (const float*)d_in[7];
    const float* b_enc2  = (const float*)d_in[8];
    const float* W_proj  = (const float*)d_in[9];
    const float* b_proj  = (const float*)d_in[10];
    const float* W_dproj = (const float*)d_in[11];
    const float* b_dproj = (const float*)d_in[12];
    const float* W_dec0  = (const float*)d_in[13];
    const float* b_dec0  = (const float*)d_in[14];
    const float* W_dec1  = (const float*)d_in[15];
    const float* b_dec1  = (const float*)d_in[16];

    float* out_recon = (float*)d_out;           // [N, IN]
    float* out_z     = (float*)d_out + N * IN;  // [G, L]

    float* buf0;  cudaGetSymbolAddress((void**)&buf0, g_buf0);
    float* buf1;  cudaGetSymbolAddress((void**)&buf1, g_buf1);
    int*   degp;  cudaGetSymbolAddress((void**)&degp, g_deg);
    float* poolp; cudaGetSymbolAddress((void**)&poolp, g_pool);
    float* cntp;  cudaGetSymbolAddress((void**)&cntp, g_cnt);

    const int T = 256;

    constexpr int SM_32_64 = (256 * 33 + 32 * 64) * 4;   // 41.0 KB
    constexpr int SM_64_64 = (256 * 65 + 64 * 64) * 4;   // 81.0 KB
    constexpr int SM_64_32 = (256 * 65 + 64 * 32) * 4;   // 73.0 KB
    static bool attr_done = false;
    if (!attr_done) {
        cudaFuncSetAttribute((const void*)k_mm<IN, H, false, true, true>,
                             cudaFuncAttributeMaxDynamicSharedMemorySize, SM_32_64);
        cudaFuncSetAttribute((const void*)k_mm<H, H, true, false, false>,
                             cudaFuncAttributeMaxDynamicSharedMemorySize, SM_64_64);
        cudaFuncSetAttribute((const void*)k_mm<H, IN, true, false, false>,
                             cudaFuncAttributeMaxDynamicSharedMemorySize, SM_64_32);
        attr_done = true;
    }

    // ---- CSR build + dinv
    cudaMemsetAsync(degp, 0, N * sizeof(int));
    cudaMemsetAsync(poolp, 0, G * H * sizeof(float));
    cudaMemsetAsync(cntp, 0, G * sizeof(float));
    k_hist<<<CDIV(E, T), T>>>(dst);
    k_scan1<<<NB_SCAN, SCAN_CHUNK>>>();
    k_scan23<<<CDIV(N, T), T>>>();
    k_fill<<<CDIV(E, T), T>>>(src, dst);

    const int MMB = CDIV(N, 256);

    // ---- enc0: aggregate x at C=32, then 32->64 matmul (+bias+relu)
    k_prescale32<<<CDIV(N * 8, T), T>>>(x, buf0);
    k_gather<IN, false, false><<<CDIV(N, 32), 256>>>(buf0, nullptr, buf1);
    k_mm<IN, H, false, true, true><<<MMB, 256, SM_32_64>>>(buf1, W_enc0, b_enc0, buf0);

    // ---- enc1
    k_mm<H, H, true, false, false><<<MMB, 256, SM_64_64>>>(buf0, W_enc1, nullptr, buf1);
    k_gather<H, true, true><<<CDIV(N, 16), 256>>>(buf1, b_enc1, buf0);

    // ---- enc2
    k_mm<H, H, true, false, false><<<MMB, 256, SM_64_64>>>(buf0, W_enc2, nullptr, buf1);
    k_gather<H, true, true><<<CDIV(N, 16), 256>>>(buf1, b_enc2, buf0);

    // ---- global mean pool + latent projection
    k_pool_acc<<<CDIV(N, 128), 256>>>(batch, buf0);
    k_z<<<1, G * L>>>(W_proj, b_proj, out_z);

    // ---- decoder broadcast
    k_dec_bcast<<<CDIV(N * 16, T), T>>>(batch, W_dproj, b_dproj, buf0);

    // ---- dec0
    k_mm<H, H, true, false, false><<<MMB, 256, SM_64_64>>>(buf0, W_dec0, nullptr, buf1);
    k_gather<H, true, true><<<CDIV(N, 16), 256>>>(buf1, b_dec0, buf0);

    // ---- dec1: 64->32 matmul (dinv-scaled), gather at C=32 into d_out
    k_mm<H, IN, true, false, false><<<MMB, 256, SM_64_32>>>(buf0, W_dec1, nullptr, buf1);
    k_gather<IN, true, false><<<CDIV(N, 32), 256>>>(buf1, b_dec1, out_recon);
}